// round 2
// baseline (speedup 1.0000x reference)
#include <cuda_runtime.h>
#include <cuda_bf16.h>

// ModernBertCanonLayer: varlen depthwise conv (K=5, radius 2) + bias + residual.
// out[i,c] = x[i,c] + bias[c] + sum_k w[c,k] * x[i+k-2, c] * [same sequence & in range]
//
// Strategy: memory-bound streaming kernel. Each thread owns a fixed float4
// column chunk (4 channels) and walks RPT consecutive tokens keeping the
// 5-row input window in registers, so every x row is fetched once.

#define CCH   768
#define C4    (CCH / 4)      // 192 float4 per row
#define RPT   64             // tokens per y-stream
#define YR    2              // y-streams per block

__global__ __launch_bounds__(C4 * YR)
void canon_kernel(const float* __restrict__ x,
                  const int*   __restrict__ cu, int ncu,
                  const float* __restrict__ weight,
                  const float* __restrict__ bias,
                  float*       __restrict__ out,
                  int T)
{
    __shared__ int s_cu[64];
    {
        int tid = threadIdx.y * blockDim.x + threadIdx.x;
        if (tid < ncu) s_cu[tid] = cu[tid];
    }
    __syncthreads();

    const int c4   = threadIdx.x;                               // 0..191
    const int base = (blockIdx.x * YR + threadIdx.y) * RPT;     // first token
    if (base >= T) return;

    // Per-thread weights: 4 channels x 5 taps, and bias (loaded once).
    float w[5][4];
    {
        const int c0 = c4 * 4;
        #pragma unroll
        for (int j = 0; j < 4; ++j)
            #pragma unroll
            for (int k = 0; k < 5; ++k)
                w[k][j] = weight[(c0 + j) * 5 + k];
    }
    const float4 b4 = reinterpret_cast<const float4*>(bias)[c4];

    const float4* __restrict__ x4  = reinterpret_cast<const float4*>(x);
    float4* __restrict__       o4  = reinterpret_cast<float4*>(out);

    // Locate sequence of token `base`: minimal s with base < cu[s+1].
    // (Handles duplicate boundaries / empty sequences like searchsorted-right.)
    int s = 0;
    while (base >= s_cu[s + 1]) ++s;
    int lo = s_cu[s], hi = s_cu[s + 1];

    // Rolling window registers: rows base-2 .. base+2.
    float4 r0, r1, r2, r3, r4;
    {
        int j;
        j = base - 2; r0 = (j >= 0) ? x4[(size_t)j * C4 + c4] : make_float4(0.f,0.f,0.f,0.f);
        j = base - 1; r1 = (j >= 0) ? x4[(size_t)j * C4 + c4] : make_float4(0.f,0.f,0.f,0.f);
        r2 = x4[(size_t)base * C4 + c4];
        j = base + 1; r3 = (j < T) ? x4[(size_t)j * C4 + c4] : make_float4(0.f,0.f,0.f,0.f);
        j = base + 2; r4 = (j < T) ? x4[(size_t)j * C4 + c4] : make_float4(0.f,0.f,0.f,0.f);
    }

    const int iend = (base + RPT < T) ? (base + RPT) : T;
    for (int i = base; i < iend; ++i) {
        // Advance sequence window (uniform across the warp: same i for all lanes).
        while (i >= hi) { ++s; lo = s_cu[s]; hi = s_cu[s + 1]; }

        float4 acc = b4;
        // Tap k contributes iff its source row j = i+k-2 lies in [lo, hi).
        // (Out-of-[0,T) also fails this test since 0 <= lo, hi <= T and i in [lo,hi).)
        {
            bool m = (i - 2 >= lo);
            float a = m ? w[0][0] : 0.f, b = m ? w[0][1] : 0.f,
                  c = m ? w[0][2] : 0.f, d = m ? w[0][3] : 0.f;
            acc.x = fmaf(a, r0.x, acc.x); acc.y = fmaf(b, r0.y, acc.y);
            acc.z = fmaf(c, r0.z, acc.z); acc.w = fmaf(d, r0.w, acc.w);
        }
        {
            bool m = (i - 1 >= lo);
            float a = m ? w[1][0] : 0.f, b = m ? w[1][1] : 0.f,
                  c = m ? w[1][2] : 0.f, d = m ? w[1][3] : 0.f;
            acc.x = fmaf(a, r1.x, acc.x); acc.y = fmaf(b, r1.y, acc.y);
            acc.z = fmaf(c, r1.z, acc.z); acc.w = fmaf(d, r1.w, acc.w);
        }
        {
            // center tap always valid (lo <= i < hi)
            acc.x = fmaf(w[2][0], r2.x, acc.x); acc.y = fmaf(w[2][1], r2.y, acc.y);
            acc.z = fmaf(w[2][2], r2.z, acc.z); acc.w = fmaf(w[2][3], r2.w, acc.w);
        }
        {
            bool m = (i + 1 < hi);
            float a = m ? w[3][0] : 0.f, b = m ? w[3][1] : 0.f,
                  c = m ? w[3][2] : 0.f, d = m ? w[3][3] : 0.f;
            acc.x = fmaf(a, r3.x, acc.x); acc.y = fmaf(b, r3.y, acc.y);
            acc.z = fmaf(c, r3.z, acc.z); acc.w = fmaf(d, r3.w, acc.w);
        }
        {
            bool m = (i + 2 < hi);
            float a = m ? w[4][0] : 0.f, b = m ? w[4][1] : 0.f,
                  c = m ? w[4][2] : 0.f, d = m ? w[4][3] : 0.f;
            acc.x = fmaf(a, r4.x, acc.x); acc.y = fmaf(b, r4.y, acc.y);
            acc.z = fmaf(c, r4.z, acc.z); acc.w = fmaf(d, r4.w, acc.w);
        }

        // residual add with center row, store
        float4 o;
        o.x = r2.x + acc.x; o.y = r2.y + acc.y;
        o.z = r2.z + acc.z; o.w = r2.w + acc.w;
        o4[(size_t)i * C4 + c4] = o;

        // shift window, fetch row i+3
        r0 = r1; r1 = r2; r2 = r3; r3 = r4;
        int jn = i + 3;
        r4 = (jn < T) ? x4[(size_t)jn * C4 + c4] : make_float4(0.f,0.f,0.f,0.f);
    }
}

extern "C" void kernel_launch(void* const* d_in, const int* in_sizes, int n_in,
                              void* d_out, int out_size)
{
    const float* x      = (const float*)d_in[0];
    const int*   cu     = (const int*)  d_in[1];
    const float* weight = (const float*)d_in[2];
    const float* bias   = (const float*)d_in[3];
    float*       out    = (float*)d_out;

    const int T   = in_sizes[0] / CCH;
    const int ncu = in_sizes[1];

    const int tokens_per_block = YR * RPT;                      // 128
    const int grid = (T + tokens_per_block - 1) / tokens_per_block;
    dim3 block(C4, YR);                                         // (192, 2) = 384 threads
    canon_kernel<<<grid, block>>>(x, cu, ncu, weight, bias, out, T);
}

// round 7
// speedup vs baseline: 1.4504x; 1.4504x over previous
#include <cuda_runtime.h>
#include <cuda_bf16.h>

// ModernBertCanonLayer: varlen depthwise conv (K=5) + bias + residual.
// Round-3 kernel: unroll-4 token groups with 4 independent prefetch LDGs
// (MLP=4 per thread) + interior fast path (no masks) + 2-wave grid shaping.

#define CCH   768
#define C4    (CCH / 4)      // 192 float4 per row
#define RPT   56             // tokens per y-stream (multiple of 4)
#define YR    2              // y-streams per block

#define ZERO4 make_float4(0.f, 0.f, 0.f, 0.f)

#define FMA4(acc, wk, r)                                   \
    acc.x = fmaf((wk)[0], (r).x, acc.x);                   \
    acc.y = fmaf((wk)[1], (r).y, acc.y);                   \
    acc.z = fmaf((wk)[2], (r).z, acc.z);                   \
    acc.w = fmaf((wk)[3], (r).w, acc.w);

#define FMA4M(acc, wk, r, m)                               \
    acc.x = fmaf((m) ? (wk)[0] : 0.f, (r).x, acc.x);       \
    acc.y = fmaf((m) ? (wk)[1] : 0.f, (r).y, acc.y);       \
    acc.z = fmaf((m) ? (wk)[2] : 0.f, (r).z, acc.z);       \
    acc.w = fmaf((m) ? (wk)[3] : 0.f, (r).w, acc.w);

// Fast token (all taps valid): 5 rows A0..A4, center A2.
#define TOKEN_FAST(it, A0, A1, A2, A3, A4)                 \
    do {                                                   \
        float4 acc = b4;                                   \
        FMA4(acc, w[0], A0); FMA4(acc, w[1], A1);          \
        FMA4(acc, w[2], A2); FMA4(acc, w[3], A3);          \
        FMA4(acc, w[4], A4);                               \
        float4 o;                                          \
        o.x = (A2).x + acc.x; o.y = (A2).y + acc.y;        \
        o.z = (A2).z + acc.z; o.w = (A2).w + acc.w;        \
        __stcs(&o4[(size_t)(it) * C4 + c4], o);            \
    } while (0)

// Slow token: advances segment and applies per-tap masks.
#define TOKEN_SLOW(it, A0, A1, A2, A3, A4)                 \
    do {                                                   \
        while ((it) >= hhi) { ++ss; llo = s_cu[ss]; hhi = s_cu[ss + 1]; } \
        float4 acc = b4;                                   \
        FMA4M(acc, w[0], A0, (it) - 2 >= llo);             \
        FMA4M(acc, w[1], A1, (it) - 1 >= llo);             \
        FMA4(acc, w[2], A2);                               \
        FMA4M(acc, w[3], A3, (it) + 1 < hhi);              \
        FMA4M(acc, w[4], A4, (it) + 2 < hhi);              \
        float4 o;                                          \
        o.x = (A2).x + acc.x; o.y = (A2).y + acc.y;        \
        o.z = (A2).z + acc.z; o.w = (A2).w + acc.w;        \
        __stcs(&o4[(size_t)(it) * C4 + c4], o);            \
    } while (0)

__global__ __launch_bounds__(C4 * YR, 2)
void canon_kernel(const float* __restrict__ x,
                  const int*   __restrict__ cu, int ncu,
                  const float* __restrict__ weight,
                  const float* __restrict__ bias,
                  float*       __restrict__ out,
                  int T)
{
    __shared__ int s_cu[64];
    {
        int tid = threadIdx.y * blockDim.x + threadIdx.x;
        if (tid < ncu) s_cu[tid] = cu[tid];
    }
    __syncthreads();

    const int c4   = threadIdx.x;                               // 0..191
    const int base = (blockIdx.x * YR + threadIdx.y) * RPT;
    if (base >= T) return;

    float w[5][4];
    {
        const int c0 = c4 * 4;
        #pragma unroll
        for (int j = 0; j < 4; ++j)
            #pragma unroll
            for (int k = 0; k < 5; ++k)
                w[k][j] = weight[(c0 + j) * 5 + k];
    }
    const float4 b4 = reinterpret_cast<const float4*>(bias)[c4];

    const float4* __restrict__ x4 = reinterpret_cast<const float4*>(x);
    float4* __restrict__       o4 = reinterpret_cast<float4*>(out);

    // Segment of token `base` (searchsorted-right; handles empty sequences).
    int s = 0;
    while (base >= s_cu[s + 1]) ++s;
    int lo = s_cu[s], hi = s_cu[s + 1];

    // Window registers: rows base-2 .. base+2.
    float4 r0, r1, r2, r3, r4;
    {
        int j;
        j = base - 2; r0 = (j >= 0) ? x4[(size_t)j * C4 + c4] : ZERO4;
        j = base - 1; r1 = (j >= 0) ? x4[(size_t)j * C4 + c4] : ZERO4;
        r2 = x4[(size_t)base * C4 + c4];
        j = base + 1; r3 = (j < T) ? x4[(size_t)j * C4 + c4] : ZERO4;
        j = base + 2; r4 = (j < T) ? x4[(size_t)j * C4 + c4] : ZERO4;
    }

    const int iend = (base + RPT < T) ? (base + RPT) : T;
    int i = base;

    // ---- unroll-4 main loop: 4 independent prefetch loads per group ----
    for (; i + 3 < iend; i += 4) {
        // Prefetch rows i+3 .. i+6 (independent -> MLP=4).
        const int j0 = i + 3, j1 = i + 4, j2 = i + 5, j3 = i + 6;
        float4 n0 = (j0 < T) ? x4[(size_t)j0 * C4 + c4] : ZERO4;
        float4 n1 = (j1 < T) ? x4[(size_t)j1 * C4 + c4] : ZERO4;
        float4 n2 = (j2 < T) ? x4[(size_t)j2 * C4 + c4] : ZERO4;
        float4 n3 = (j3 < T) ? x4[(size_t)j3 * C4 + c4] : ZERO4;

        // Catch segment window up to token i (warp-uniform).
        while (i >= hi) { ++s; lo = s_cu[s]; hi = s_cu[s + 1]; }

        if (i - 2 >= lo && i + 5 < hi) {
            // Interior fast path: tokens i..i+3 have all taps in-segment.
            TOKEN_FAST(i    , r0, r1, r2, r3, r4);
            TOKEN_FAST(i + 1, r1, r2, r3, r4, n0);
            TOKEN_FAST(i + 2, r2, r3, r4, n0, n1);
            TOKEN_FAST(i + 3, r3, r4, n0, n1, n2);
        } else {
            int ss = s, llo = lo, hhi = hi;
            TOKEN_SLOW(i    , r0, r1, r2, r3, r4);
            TOKEN_SLOW(i + 1, r1, r2, r3, r4, n0);
            TOKEN_SLOW(i + 2, r2, r3, r4, n0, n1);
            TOKEN_SLOW(i + 3, r3, r4, n0, n1, n2);
        }

        // Shift window to rows (i+4)-2 .. (i+4)+2 = i+2 .. i+6.
        r0 = r4; r1 = n0; r2 = n1; r3 = n2; r4 = n3;
    }

    // ---- scalar tail (<= 3 tokens) ----
    for (; i < iend; ++i) {
        while (i >= hi) { ++s; lo = s_cu[s]; hi = s_cu[s + 1]; }
        int ss = s, llo = lo, hhi = hi;
        TOKEN_SLOW(i, r0, r1, r2, r3, r4);
        int jn = i + 3;
        float4 nn = (jn < T) ? x4[(size_t)jn * C4 + c4] : ZERO4;
        r0 = r1; r1 = r2; r2 = r3; r3 = r4; r4 = nn;
    }
}

extern "C" void kernel_launch(void* const* d_in, const int* in_sizes, int n_in,
                              void* d_out, int out_size)
{
    const float* x      = (const float*)d_in[0];
    const int*   cu     = (const int*)  d_in[1];
    const float* weight = (const float*)d_in[2];
    const float* bias   = (const float*)d_in[3];
    float*       out    = (float*)d_out;

    const int T   = in_sizes[0] / CCH;
    const int ncu = in_sizes[1];

    const int tokens_per_block = YR * RPT;                      // 112
    const int grid = (T + tokens_per_block - 1) / tokens_per_block;  // 586
    dim3 block(C4, YR);                                         // (192, 2) = 384 threads
    canon_kernel<<<grid, block>>>(x, cu, ncu, weight, bias, out, T);
}